// round 1
// baseline (speedup 1.0000x reference)
#include <cuda_runtime.h>
#include <cuda_bf16.h>
#include <cstddef>

// ---------------------------------------------------------------------------
// Problem constants
// ---------------------------------------------------------------------------
#define N_NODES 100
#define IN_C    65536
#define OUT_C   60
#define N_EDGES 1600
#define NCOLS   360          // 2 heads * 3 cheb orders * 60
#define NSPLIT  96           // K-splits for the big GEMM

// ---------------------------------------------------------------------------
// Scratch (no cudaMalloc allowed)
// ---------------------------------------------------------------------------
__device__ float g_A[N_NODES * N_NODES];     // dense normalized adjacency (Â)
__device__ float g_Y[N_NODES * NCOLS];       // x @ Wcat   [100, 360]
__device__ float g_U[2 * N_NODES * OUT_C];   // Â @ Y2 per head
__device__ float g_emb[2 * N_NODES * OUT_C]; // final embeddings per head
__device__ float g_V[2 * OUT_C];             // vnr sums per head

// ---------------------------------------------------------------------------
// Kernel 1: prep — zero Y/A, build Â from edges, vnr sums, init outputs w/ bias
// ---------------------------------------------------------------------------
__global__ void prep_kernel(const int* __restrict__ ei,
                            const float* __restrict__ vnr,
                            const float* __restrict__ avw, const float* __restrict__ avb,
                            const float* __restrict__ cvw, const float* __restrict__ cvb,
                            const float* __restrict__ afb, const float* __restrict__ cfb,
                            float* __restrict__ out, int out_size) {
    __shared__ float sdeg[N_NODES];
    const int t = threadIdx.x;  // 256 threads

    for (int i = t; i < N_NODES * NCOLS; i += 256) g_Y[i] = 0.f;
    for (int i = t; i < N_NODES * N_NODES; i += 256) g_A[i] = 0.f;
    if (t < N_NODES) sdeg[t] = 0.f;
    __syncthreads();

    // deg = segment_sum(ones, src)
    for (int e = t; e < N_EDGES; e += 256) atomicAdd(&sdeg[ei[e]], 1.f);
    __syncthreads();
    if (t < N_NODES) {
        float d = sdeg[t];
        sdeg[t] = (d > 0.f) ? rsqrtf(fmaxf(d, 1.f)) : 0.f;
    }
    __syncthreads();

    // Â[dst, src] += -dinv[src]*dinv[dst]
    for (int e = t; e < N_EDGES; e += 256) {
        int s = ei[e];
        int d = ei[N_EDGES + e];
        atomicAdd(&g_A[d * N_NODES + s], -sdeg[s] * sdeg[d]);
    }

    // vnr sums: sum_i v[i]*w[i][c] + b[i][c]
    if (t < OUT_C) {
        float va = 0.f, vc = 0.f;
        #pragma unroll
        for (int i = 0; i < 3; i++) {
            float v = vnr[i];
            va += v * avw[i * OUT_C + t] + avb[i * OUT_C + t];
            vc += v * cvw[i * OUT_C + t] + cvb[i * OUT_C + t];
        }
        g_V[t] = va;
        g_V[OUT_C + t] = vc;
    }

    // init outputs with biases (fc kernel atomically accumulates on top)
    for (int j = t; j < out_size; j += 256)
        out[j] = (j < 100) ? afb[j] : ((j == 100) ? cfb[0] : 0.f);
}

// ---------------------------------------------------------------------------
// Kernel 2: the big fused GEMM  Y[100,360] = x[100,65536] @ Wcat[65536,360]
//   Wcat column c: head = c/180, k = (c%180)/60, ch = c%60
//   Block tile: 100m x 128n, split-K (96 splits), 320 threads, thread tile 5x8
// ---------------------------------------------------------------------------
__global__ __launch_bounds__(320, 2)
void gemm_kernel(const float* __restrict__ x,
                 const float* __restrict__ aw,
                 const float* __restrict__ cw) {
    __shared__ float xs[N_NODES][36];        // [m][k]  (KK=32 + pad 4)
    __shared__ float ws[32][132];            // [k][n]  (NT=128 + pad 4)
    __shared__ const float* wptr[128];       // per-column base pointer

    const int t  = threadIdx.x;
    const int tx = t & 15;       // n-group 0..15
    const int ty = t >> 4;       // m-group 0..19
    const int nb0 = blockIdx.x * 128;

    // K range for this split; rounded to multiples of 4 so ranges tile exactly
    int k0 = (int)(((long long)blockIdx.y * IN_C) / NSPLIT) & ~3;
    int k1 = (int)(((long long)(blockIdx.y + 1) * IN_C) / NSPLIT) & ~3;

    if (t < 128) {
        int col = nb0 + t;
        const float* p = nullptr;
        if (col < NCOLS) {
            int h  = col / 180;
            int r  = col % 180;
            int kk = r / OUT_C;
            int ch = r % OUT_C;
            p = (h ? cw : aw) + (size_t)kk * IN_C * OUT_C + ch;
        }
        wptr[t] = p;
    }

    float acc[5][8];
    #pragma unroll
    for (int i = 0; i < 5; i++)
        #pragma unroll
        for (int j = 0; j < 8; j++) acc[i][j] = 0.f;

    __syncthreads();

    for (int kp = k0; kp < k1; kp += 32) {
        const int klen = min(32, k1 - kp);      // always a multiple of 4
        const int kq = klen >> 2;               // float4s per x row

        // ---- load x tile [100][klen] (float4, coalesced, conflict-free STS)
        for (int l = t; l < N_NODES * 8; l += 320) {
            int m = l >> 3, k4 = l & 7;
            if (k4 < kq) {
                float4 v = *(const float4*)(x + (size_t)m * IN_C + kp + (k4 << 2));
                *(float4*)&xs[m][k4 << 2] = v;
            }
        }
        // ---- load w tile [klen][128] (coalesced across n)
        for (int l = t; l < 32 * 128; l += 320) {
            int n = l & 127, k = l >> 7;
            float v = 0.f;
            const float* p = wptr[n];
            if (p != nullptr && k < klen) v = p[(size_t)(kp + k) * OUT_C];
            ws[k][n] = v;
        }
        __syncthreads();

        // ---- 5x8 register-tile outer product over k
        #pragma unroll 4
        for (int k = 0; k < klen; k++) {
            float xr[5];
            #pragma unroll
            for (int i = 0; i < 5; i++) xr[i] = xs[ty * 5 + i][k];
            float4 w0 = *(const float4*)&ws[k][tx * 8];
            float4 w1 = *(const float4*)&ws[k][tx * 8 + 4];
            float wr[8] = {w0.x, w0.y, w0.z, w0.w, w1.x, w1.y, w1.z, w1.w};
            #pragma unroll
            for (int i = 0; i < 5; i++)
                #pragma unroll
                for (int j = 0; j < 8; j++)
                    acc[i][j] += xr[i] * wr[j];
        }
        __syncthreads();
    }

    // ---- split-K reduction
    #pragma unroll
    for (int i = 0; i < 5; i++) {
        int m = ty * 5 + i;
        #pragma unroll
        for (int j = 0; j < 8; j++) {
            int n = nb0 + tx * 8 + j;
            if (n < NCOLS) atomicAdd(&g_Y[m * NCOLS + n], acc[i][j]);
        }
    }
}

// ---------------------------------------------------------------------------
// Kernel 3: U = Â @ Y2  (per head).  grid (100, 2), 64 threads (60 active)
// ---------------------------------------------------------------------------
__global__ void u_kernel() {
    const int m = blockIdx.x, h = blockIdx.y, c = threadIdx.x;
    if (c >= OUT_C) return;
    const float* Arow = g_A + m * N_NODES;
    const float* Y2 = g_Y + h * 180 + 120 + c;
    float acc = 0.f;
    #pragma unroll 10
    for (int s = 0; s < N_NODES; s++)
        acc += Arow[s] * Y2[s * NCOLS];
    g_U[h * N_NODES * OUT_C + m * OUT_C + c] = acc;
}

// ---------------------------------------------------------------------------
// Kernel 4: emb = tanh(Y0 - Y2 + Â@(Y1 + 2U) + cheb_b) + vnr_sum
// ---------------------------------------------------------------------------
__global__ void v_kernel(const float* __restrict__ acb,
                         const float* __restrict__ ccb) {
    const int m = blockIdx.x, h = blockIdx.y, c = threadIdx.x;
    if (c >= OUT_C) return;
    const float* Arow = g_A + m * N_NODES;
    const float* Y1 = g_Y + h * 180 + 60 + c;
    const float* U  = g_U + h * N_NODES * OUT_C + c;
    float acc = 0.f;
    #pragma unroll 10
    for (int s = 0; s < N_NODES; s++)
        acc += Arow[s] * (Y1[s * NCOLS] + 2.f * U[s * OUT_C]);
    const float* Yr = g_Y + m * NCOLS + h * 180;
    float pre = Yr[c] - Yr[120 + c] + acc + (h ? ccb[c] : acb[c]);
    g_emb[h * N_NODES * OUT_C + m * OUT_C + c] = tanhf(pre) + g_V[h * OUT_C + c];
}

// ---------------------------------------------------------------------------
// Kernel 5: heads.  logits[j] = emb_a_flat . afc_w[:,j] (+bias, pre-seeded)
//           value    = emb_c_flat . cfc_w            (+bias, pre-seeded)
// grid 24 blocks x 128 threads, each handles 250 rows of the 6000-dot
// ---------------------------------------------------------------------------
__global__ void fc_kernel(const float* __restrict__ afw,
                          const float* __restrict__ cfw,
                          float* __restrict__ out, int out_size) {
    __shared__ float ea[250], ec[250];
    __shared__ float red[4];
    const int b = blockIdx.x, t = threadIdx.x;
    const int i0 = b * 250;

    for (int i = t; i < 250; i += 128) {
        ea[i] = g_emb[i0 + i];
        ec[i] = g_emb[6000 + i0 + i];
    }
    __syncthreads();

    if (t < 100) {
        float acc = 0.f;
        #pragma unroll 5
        for (int i = 0; i < 250; i++)
            acc += ea[i] * afw[(size_t)(i0 + i) * 100 + t];
        atomicAdd(&out[t], acc);
    }

    float cacc = 0.f;
    for (int i = t; i < 250; i += 128) cacc += ec[i] * cfw[i0 + i];
    #pragma unroll
    for (int off = 16; off > 0; off >>= 1)
        cacc += __shfl_down_sync(0xffffffffu, cacc, off);
    if ((t & 31) == 0) red[t >> 5] = cacc;
    __syncthreads();
    if (t == 0 && out_size > 100)
        atomicAdd(&out[100], red[0] + red[1] + red[2] + red[3]);
}

// ---------------------------------------------------------------------------
// Launch
// ---------------------------------------------------------------------------
extern "C" void kernel_launch(void* const* d_in, const int* in_sizes, int n_in,
                              void* d_out, int out_size) {
    const float* x   = (const float*)d_in[0];   // substrate_features [100,65536]
    const int*   ei  = (const int*)  d_in[1];   // edge_index [2,1600]
    const float* vnr = (const float*)d_in[2];   // vnr_features [1,3]
    const float* aw  = (const float*)d_in[3];   // actor_cheb_w [3,65536,60]
    const float* acb = (const float*)d_in[4];   // actor_cheb_b [60]
    const float* cw  = (const float*)d_in[5];   // critic_cheb_w
    const float* ccb = (const float*)d_in[6];   // critic_cheb_b
    const float* avw = (const float*)d_in[7];   // actor_vnr_w [3,60]
    const float* avb = (const float*)d_in[8];
    const float* cvw = (const float*)d_in[9];
    const float* cvb = (const float*)d_in[10];
    const float* afw = (const float*)d_in[11];  // actor_fc_w [6000,100]
    const float* afb = (const float*)d_in[12];
    const float* cfw = (const float*)d_in[13];  // critic_fc_w [6000,1]
    const float* cfb = (const float*)d_in[14];
    float* out = (float*)d_out;

    prep_kernel<<<1, 256>>>(ei, vnr, avw, avb, cvw, cvb, afb, cfb, out, out_size);
    gemm_kernel<<<dim3(3, NSPLIT), 320>>>(x, aw, cw);
    u_kernel<<<dim3(N_NODES, 2), 64>>>();
    v_kernel<<<dim3(N_NODES, 2), 64>>>(acb, ccb);
    fc_kernel<<<24, 128>>>(afw, cfw, out, out_size);
}